// round 10
// baseline (speedup 1.0000x reference)
#include <cuda_runtime.h>
#include <math.h>

// Fixed problem geometry (setup_inputs: inp (8,3,224,224) fp32,
// tau_min=1, tau_max=60, ntau=8, num_angles=12, stride=2).
#define B_    8
#define F_    3
#define H_    224
#define W_    224
#define HS_   112
#define WS_   112
#define NTAU_ 8
#define NANG_ 12
#define NGRP_ (B_ * F_ * NTAU_ * NANG_)   // 192 (bf,t,a) groups
#define IPT_  16                          // i-rows per block
#define NTI_  (HS_ / IPT_)                // 7
#define IPH_  (IPT_ / 2)                  // i-rows per thread in odd path (8)

__global__ __launch_bounds__(128)
void logpolar_kernel(const float* __restrict__ inp, float* __restrict__ out)
{
    const int g   = blockIdx.y;
    const int tid = threadIdx.x;

    const int a  = g % NANG_;
    const int t  = (g / NANG_) % NTAU_;
    const int bf = g / (NANG_ * NTAU_);

    // Group offsets in fp32 (MUFU): bilinear sampling is continuous in the
    // offset, so ~1e-7 offset error -> ~1e-5 output error (tol 1e-3).
    const float tau   = exp2f((float)t * 0.8438415136583599f);  // log2(60)/7
    const float theta = (float)a * 0.5235987755982988f - 3.14159265358979323846f;
    float sth, cth;
    __sincosf(theta, &sth, &cth);
    const float yo = tau * sth;
    const float xo = tau * cth;

    const float flx = floorf(xo);
    const float fly = floorf(yo);
    const float wx  = xo - flx;            // uniform frac (2j, 2i are integers)
    const float wy  = yo - fly;
    const int   fl  = (int)flx;
    const int   fli = (int)fly;

    const float w00 = (1.0f - wy) * (1.0f - wx);
    const float w01 = (1.0f - wy) * wx;
    const float w10 = wy * (1.0f - wx);
    const float w11 = wy * wx;

    const int i0 = blockIdx.x * IPT_;
    const float* base = inp + (size_t)bf * (H_ * W_);

    // Block-uniform: all IPT_ iterations' rows in-bounds?
    const int  y0blk = fli + 2 * i0;
    const bool fastY = (y0blk >= 0) && (y0blk + 2 * (IPT_ - 1) + 1 < H_);

    if ((fl & 1) == 0) {
        // ---- Even parity: 1 output/thread, (v(x0), v(x0+1)) = one float2 ----
        const int j = tid;
        if (j >= WS_) return;
        const int x0 = fl + 2 * j;

        const bool  m  = (x0 >= 0) && (x0 <= W_ - 2);   // all-or-nothing (W even)
        const float mf = m ? 1.0f : 0.0f;
        const float a00 = w00 * mf, a01 = w01 * mf;
        const float a10 = w10 * mf, a11 = w11 * mf;
        const int   o   = m ? x0 : 0;

        const float2* p = (const float2*)(base + y0blk * W_ + o);
        float* op = out + ((size_t)g * HS_ + i0) * WS_ + j;

        if (fastY) {
            #pragma unroll
            for (int it = 0; it < IPT_; it++) {
                float2 r0 = __ldg(p);
                float2 r1 = __ldg(p + (W_ / 2));
                *op = r0.x * a00 + r0.y * a01 + r1.x * a10 + r1.y * a11;
                p  += W_;          // +2 input rows (float2 units)
                op += WS_;
            }
        } else {
            int y = y0blk;
            #pragma unroll
            for (int it = 0; it < IPT_; it++) {
                float2 r0 = ((unsigned)y       < H_) ? __ldg(p)            : make_float2(0.f, 0.f);
                float2 r1 = ((unsigned)(y + 1) < H_) ? __ldg(p + (W_ / 2)) : make_float2(0.f, 0.f);
                *op = r0.x * a00 + r0.y * a01 + r1.x * a10 + r1.y * a11;
                y  += 2;
                p  += W_;
                op += WS_;
            }
        }
    } else {
        // ---- Odd parity: 2 outputs/thread in j, half the i-range each ----
        // tid -> (l, half): l = tid % 56 selects output pair (2l, 2l+1),
        // half selects i-rows [i0 + half*IPH_, ...). 112 active lanes.
        // Taps x00..x00+3 (x00 = fl+4l, odd) from 3 aligned float2 loads:
        //   q0 @ (x00-1): .y = v(x00)
        //   q1 @ (x00+1): .x = v(x00+1), .y = v(x00+2)
        //   q2 @ (x00+3): .x = v(x00+3)
        if (tid >= 112) return;
        const int l    = (tid >= 56) ? (tid - 56) : tid;
        const int half = (tid >= 56) ? 1 : 0;
        const int x00  = fl + 4 * l;
        const int ih   = i0 + half * IPH_;
        const int y0   = fli + 2 * ih;

        const bool  m0 = (x00 >= 0)     && (x00 < W_);
        const bool  m1 = (x00 + 1 >= 0) && (x00 + 1 < W_);
        const bool  m2 = (x00 + 2 >= 0) && (x00 + 2 < W_);
        const bool  m3 = (x00 + 3 >= 0) && (x00 + 3 < W_);
        const float f0 = m0 ? 1.0f : 0.0f;
        const float f1 = m1 ? 1.0f : 0.0f;
        const float f2 = m2 ? 1.0f : 0.0f;
        const float f3 = m3 ? 1.0f : 0.0f;

        const float e00 = w00 * f0, e01 = w01 * f1;     // output 2l
        const float e10 = w10 * f0, e11 = w11 * f1;
        const float h00 = w00 * f2, h01 = w01 * f3;     // output 2l+1
        const float h10 = w10 * f2, h11 = w11 * f3;

        // Clamped, even (8B-aligned), always-in-row load offsets.
        const int o0 = m0 ? (x00 - 1) : 0;
        const int o1 = m1 ? (x00 + 1) : 0;
        const int o2 = m3 ? (x00 + 3) : 0;

        const float2* q0 = (const float2*)(base + y0 * W_ + o0);
        const float2* q1 = (const float2*)(base + y0 * W_ + o1);
        const float2* q2 = (const float2*)(base + y0 * W_ + o2);
        float2* op = (float2*)(out + ((size_t)g * HS_ + ih) * WS_ + 2 * l);

        if (fastY) {
            #pragma unroll
            for (int it = 0; it < IPH_; it++) {
                float2 a0 = __ldg(q0);
                float2 b0 = __ldg(q1);
                float2 c0 = __ldg(q2);
                float2 a1 = __ldg(q0 + (W_ / 2));
                float2 b1 = __ldg(q1 + (W_ / 2));
                float2 c1 = __ldg(q2 + (W_ / 2));
                float2 r;
                r.x = a0.y * e00 + b0.x * e01 + a1.y * e10 + b1.x * e11;
                r.y = b0.y * h00 + c0.x * h01 + b1.y * h10 + c1.x * h11;
                *op = r;
                q0 += W_;  q1 += W_;  q2 += W_;   // +2 input rows
                op += WS_ / 2;
            }
        } else {
            int y = y0;
            #pragma unroll
            for (int it = 0; it < IPH_; it++) {
                bool vr0 = (unsigned)y       < H_;
                bool vr1 = (unsigned)(y + 1) < H_;
                float2 z  = make_float2(0.f, 0.f);
                float2 a0 = vr0 ? __ldg(q0)            : z;
                float2 b0 = vr0 ? __ldg(q1)            : z;
                float2 c0 = vr0 ? __ldg(q2)            : z;
                float2 a1 = vr1 ? __ldg(q0 + (W_ / 2)) : z;
                float2 b1 = vr1 ? __ldg(q1 + (W_ / 2)) : z;
                float2 c1 = vr1 ? __ldg(q2 + (W_ / 2)) : z;
                float2 r;
                r.x = a0.y * e00 + b0.x * e01 + a1.y * e10 + b1.x * e11;
                r.y = b0.y * h00 + c0.x * h01 + b1.y * h10 + c1.x * h11;
                *op = r;
                y  += 2;
                q0 += W_;  q1 += W_;  q2 += W_;
                op += WS_ / 2;
            }
        }
    }
}

extern "C" void kernel_launch(void* const* d_in, const int* in_sizes, int n_in,
                              void* d_out, int out_size) {
    const float* inp = (const float*)d_in[0];
    float*       out = (float*)d_out;

    dim3 grid(NTI_, NGRP_);   // (7, 192) = 1344 blocks
    logpolar_kernel<<<grid, 128>>>(inp, out);
}

// round 11
// speedup vs baseline: 1.1923x; 1.1923x over previous
#include <cuda_runtime.h>
#include <math.h>

// Fixed problem geometry (setup_inputs: inp (8,3,224,224) fp32,
// tau_min=1, tau_max=60, ntau=8, num_angles=12, stride=2).
#define B_    8
#define F_    3
#define H_    224
#define W_    224
#define HS_   112
#define WS_   112
#define NTAU_ 8
#define NANG_ 12
#define NOFF_ (NTAU_ * NANG_)             // 96
#define NGRP_ (B_ * F_ * NTAU_ * NANG_)   // 192 (bf,t,a) groups
#define IPT_  16                          // i-rows per block
#define NTI_  (HS_ / IPT_)                // 7

// Offsets live in the kernel-parameter constant bank, indexed k = t*NANG + a
// (matching g % 96 for g = ((bf*NTAU + t)*NANG + a)).
struct OffTable {
    float y[NOFF_];
    float x[NOFF_];
};

__global__ __launch_bounds__(128)
void logpolar_kernel(const float* __restrict__ inp, float* __restrict__ out,
                     const __grid_constant__ OffTable ot)
{
    const int g = blockIdx.y;
    const int j = threadIdx.x;
    if (j >= WS_) return;

    const int k  = g % NOFF_;             // t*NANG + a
    const int bf = g / NOFF_;

    const float yo = ot.y[k];             // exact fp64->fp32 offsets (host)
    const float xo = ot.x[k];

    const float flx = floorf(xo);
    const float fly = floorf(yo);
    const float wx  = xo - flx;           // uniform frac (2j, 2i are integers)
    const float wy  = yo - fly;
    const int   fl  = (int)flx;
    const int   fli = (int)fly;

    const float w00 = (1.0f - wy) * (1.0f - wx);
    const float w01 = (1.0f - wy) * wx;
    const float w10 = wy * (1.0f - wx);
    const float w11 = wy * wx;

    const int x0 = fl + 2 * j;            // left tap column for output j
    const int i0 = blockIdx.x * IPT_;
    const int y0 = fli + 2 * i0;          // top tap row of first iteration

    const float* base = inp + (size_t)bf * (H_ * W_);
    float* op = out + ((size_t)g * HS_ + i0) * WS_ + j;

    // Block-uniform: all IPT_ iterations' rows in-bounds?
    const bool fastY = (y0 >= 0) && (y0 + 2 * (IPT_ - 1) + 1 < H_);

    if ((fl & 1) == 0) {
        // ---- Even parity: (v(x0), v(x0+1)) is one aligned float2 ----
        const bool  m  = (x0 >= 0) && (x0 <= W_ - 2);   // all-or-nothing (W even)
        const float mf = m ? 1.0f : 0.0f;
        const float a00 = w00 * mf, a01 = w01 * mf;
        const float a10 = w10 * mf, a11 = w11 * mf;
        const int   o   = m ? x0 : 0;

        const float2* p = (const float2*)(base + y0 * W_ + o);

        if (fastY) {
            #pragma unroll
            for (int it = 0; it < IPT_; it++) {
                float2 r0 = __ldg(p);
                float2 r1 = __ldg(p + (W_ / 2));
                *op = r0.x * a00 + r0.y * a01 + r1.x * a10 + r1.y * a11;
                p  += W_;          // +2 input rows (float2 units)
                op += WS_;
            }
        } else {
            int y = y0;
            #pragma unroll
            for (int it = 0; it < IPT_; it++) {
                float2 r0 = ((unsigned)y       < H_) ? __ldg(p)            : make_float2(0.f, 0.f);
                float2 r1 = ((unsigned)(y + 1) < H_) ? __ldg(p + (W_ / 2)) : make_float2(0.f, 0.f);
                *op = r0.x * a00 + r0.y * a01 + r1.x * a10 + r1.y * a11;
                y  += 2;
                p  += W_;
                op += WS_;
            }
        }
    } else {
        // ---- Odd parity: two aligned float2 streams ----
        // p0 @ (x0-1): .y = v(x0);  p1 @ (x0+1): .x = v(x0+1)
        const bool  m0 = (x0 >= 0)     && (x0 < W_);
        const bool  m1 = (x0 + 1 >= 0) && (x0 + 1 < W_);
        const float f0 = m0 ? 1.0f : 0.0f;
        const float f1 = m1 ? 1.0f : 0.0f;
        const float a00 = w00 * f0, a01 = w01 * f1;
        const float a10 = w10 * f0, a11 = w11 * f1;
        const int   o0  = m0 ? (x0 - 1) : 0;
        const int   o1  = m1 ? (x0 + 1) : 0;

        const float2* p0 = (const float2*)(base + y0 * W_ + o0);
        const float2* p1 = (const float2*)(base + y0 * W_ + o1);

        if (fastY) {
            #pragma unroll
            for (int it = 0; it < IPT_; it++) {
                float2 r0a = __ldg(p0);
                float2 r0b = __ldg(p1);
                float2 r1a = __ldg(p0 + (W_ / 2));
                float2 r1b = __ldg(p1 + (W_ / 2));
                *op = r0a.y * a00 + r0b.x * a01 + r1a.y * a10 + r1b.x * a11;
                p0 += W_;
                p1 += W_;
                op += WS_;
            }
        } else {
            int y = y0;
            #pragma unroll
            for (int it = 0; it < IPT_; it++) {
                bool vr0 = (unsigned)y       < H_;
                bool vr1 = (unsigned)(y + 1) < H_;
                float2 r0a = vr0 ? __ldg(p0)            : make_float2(0.f, 0.f);
                float2 r0b = vr0 ? __ldg(p1)            : make_float2(0.f, 0.f);
                float2 r1a = vr1 ? __ldg(p0 + (W_ / 2)) : make_float2(0.f, 0.f);
                float2 r1b = vr1 ? __ldg(p1 + (W_ / 2)) : make_float2(0.f, 0.f);
                *op = r0a.y * a00 + r0b.x * a01 + r1a.y * a10 + r1b.x * a11;
                y  += 2;
                p0 += W_;
                p1 += W_;
                op += WS_;
            }
        }
    }
}

extern "C" void kernel_launch(void* const* d_in, const int* in_sizes, int n_in,
                              void* d_out, int out_size) {
    const float* inp = (const float*)d_in[0];
    float*       out = (float*)d_out;

    // Exact offsets in fp64 on the host (matches the reference's numpy math),
    // passed by value through the kernel-param constant bank.
    OffTable ot;
    const double c = pow(60.0, 1.0 / 7.0) - 1.0;
    for (int t = 0; t < NTAU_; t++) {
        const double tau = pow(1.0 + c, (double)t);
        for (int a = 0; a < NANG_; a++) {
            const double theta = (double)a * (2.0 * M_PI / (double)NANG_) - M_PI;
            ot.y[t * NANG_ + a] = (float)(tau * sin(theta));
            ot.x[t * NANG_ + a] = (float)(tau * cos(theta));
        }
    }

    dim3 grid(NTI_, NGRP_);   // (7, 192) = 1344 blocks, single wave
    logpolar_kernel<<<grid, 128>>>(inp, out, ot);
}